// round 6
// baseline (speedup 1.0000x reference)
#include <cuda_runtime.h>
#include <math.h>

typedef unsigned long long u64;

__device__ __forceinline__ u64 pk2(float lo, float hi) {
    u64 r; asm("mov.b64 %0, {%1, %2};" : "=l"(r) : "f"(lo), "f"(hi)); return r;
}
__device__ __forceinline__ void upk2(u64 v, float& lo, float& hi) {
    asm("mov.b64 {%0, %1}, %2;" : "=f"(lo), "=f"(hi) : "l"(v));
}
// packed fp32x2 FMA (Blackwell): d = a*b + c on both 32-bit lanes
__device__ __forceinline__ u64 fma2(u64 a, u64 b, u64 c) {
    u64 d; asm("fma.rn.f32x2 %0, %1, %2, %3;" : "=l"(d) : "l"(a), "l"(b), "l"(c)); return d;
}
__device__ __forceinline__ float gelu_f(float x) {
    return 0.5f * x * (1.0f + erff(x * 0.70710678118654752440f));
}

#define HT 36  // row stride (floats) for transposed activation tiles: 144B = 16B-aligned, conflict-padded

// Dynamic SMEM layout (floats):
//   [0      , 4608 )  hT   [128][36]  (token-MLP hidden, d-major)
//   [4608   , 13824)  x2T  [256][36]  (expanded hidden, f-major)  -- overlaid later by pool[256], pn[256]
//   [13824  , 13952)  tok  [32][4]
//   [13952  , 14080)  ln1_g
//   [14080  , 14208)  ln1_b
//   [14208  , 14224)  red
//   [14224  , 14240)  sc   (0:mu 1:sigma 4..6:xq 8..10:eg 12:mean 13:inv)
#define SMEM_FLOATS 14240
#define SMEM_BYTES  (SMEM_FLOATS * 4)

__global__ void __launch_bounds__(128, 4)
ff_fused_kernel(const float* __restrict__ xyt_q, const float* __restrict__ obs_coords,
                const float* __restrict__ obs_vals, const int* __restrict__ nb_idx,
                const float* __restrict__ log_gammas,
                const float* __restrict__ w_in, const float* __restrict__ b_in,
                const float* __restrict__ ln1_g, const float* __restrict__ ln1_b,
                const float* __restrict__ w1, const float* __restrict__ b1,
                const float* __restrict__ w2, const float* __restrict__ b2,
                const float* __restrict__ hln_g, const float* __restrict__ hln_b,
                const float* __restrict__ hw1, const float* __restrict__ hb1,
                const float* __restrict__ hw2, const float* __restrict__ hb2,
                float* __restrict__ out)
{
    extern __shared__ float sm[];
    float* sm_hT   = sm;
    float* sm_x2T  = sm + 4608;
    float* sm_pool = sm_x2T;          // reuse (after x2T consumed)
    float* sm_pn   = sm_x2T + 256;    // reuse
    float* sm_tok  = sm + 13824;
    float* sm_g    = sm + 13952;
    float* sm_b    = sm + 14080;
    float* sm_red  = sm + 14208;
    float* sm_sc   = sm + 14224;

    const int t    = threadIdx.x;
    const int q    = blockIdx.x;
    const int lane = t & 31;
    const int wid  = t >> 5;

    // ---- Phase 0a: preload LN1 params + query coords/gammas ----
    sm_g[t] = ln1_g[t];
    sm_b[t] = ln1_b[t];
    if (t < 3) {
        sm_sc[4 + t] = xyt_q[q * 3 + t];
        sm_sc[8 + t] = expf(log_gammas[t]);
    }
    __syncthreads();

    // ---- Phase 0b: gather neighbors, mu/sigma, build tokens (warp 0) ----
    if (t < 32) {
        int idx  = nb_idx[q * 32 + t];
        float cx = obs_coords[idx * 3 + 0];
        float cy = obs_coords[idx * 3 + 1];
        float cz = obs_coords[idx * 3 + 2];
        float v  = obs_vals[idx];
        float s = v, s2 = v * v;
        #pragma unroll
        for (int o = 16; o; o >>= 1) {
            s  += __shfl_xor_sync(0xffffffffu, s,  o);
            s2 += __shfl_xor_sync(0xffffffffu, s2, o);
        }
        float mu   = s * (1.0f / 32.0f);
        float varu = fmaxf((s2 - s * mu) * (1.0f / 31.0f), 0.0f);  // unbiased (ddof=1)
        float sig  = fmaxf(sqrtf(varu), 1e-3f);
        if (t == 0) { sm_sc[0] = mu; sm_sc[1] = sig; }
        float4 tk;
        tk.x = (cx - sm_sc[4]) * sm_sc[8];
        tk.y = (cy - sm_sc[5]) * sm_sc[9];
        tk.z = (cz - sm_sc[6]) * sm_sc[10];
        tk.w = (v - mu) / sig;
        ((float4*)sm_tok)[t] = tk;
    }
    __syncthreads();

    // ---- Phase 1: h[k][d] = gelu(tokens @ w_in^T + b_in); thread = channel d ----
    {
        float4 wv = ((const float4*)w_in)[t];   // w_in row d = exactly one float4
        float  bw = b_in[t];
        float* hrow = sm_hT + t * HT;
        #pragma unroll
        for (int k = 0; k < 32; k++) {
            float4 tk = ((const float4*)sm_tok)[k];
            float a = fmaf(tk.w, wv.w, fmaf(tk.z, wv.z, fmaf(tk.y, wv.y, fmaf(tk.x, wv.x, bw))));
            hrow[k] = gelu_f(a);
        }
    }
    __syncthreads();

    // ---- Phase 2: LayerNorm over D per token (warp per 8 tokens), in-place ----
    {
        #pragma unroll
        for (int kk = 0; kk < 8; kk++) {
            int k = wid * 8 + kk;
            float x0 = sm_hT[(lane      ) * HT + k];
            float x1 = sm_hT[(lane + 32 ) * HT + k];
            float x2 = sm_hT[(lane + 64 ) * HT + k];
            float x3 = sm_hT[(lane + 96 ) * HT + k];
            float s  = x0 + x1 + x2 + x3;
            float s2 = x0*x0 + x1*x1 + x2*x2 + x3*x3;
            #pragma unroll
            for (int o = 16; o; o >>= 1) {
                s  += __shfl_xor_sync(0xffffffffu, s,  o);
                s2 += __shfl_xor_sync(0xffffffffu, s2, o);
            }
            float m   = s * (1.0f / 128.0f);
            float inv = rsqrtf(s2 * (1.0f / 128.0f) - m * m + 1e-5f);
            sm_hT[(lane      ) * HT + k] = (x0 - m) * inv * sm_g[lane      ] + sm_b[lane      ];
            sm_hT[(lane + 32 ) * HT + k] = (x1 - m) * inv * sm_g[lane + 32 ] + sm_b[lane + 32 ];
            sm_hT[(lane + 64 ) * HT + k] = (x2 - m) * inv * sm_g[lane + 64 ] + sm_b[lane + 64 ];
            sm_hT[(lane + 96 ) * HT + k] = (x3 - m) * inv * sm_g[lane + 96 ] + sm_b[lane + 96 ];
        }
    }
    __syncthreads();

    // ---- Phase 3: x2[k][f] = gelu(xn @ w1^T + b1); thread owns f0=t, f1=t+128 ----
    // f32x2 lanes = token pair (2j, 2j+1); weight packed once per d.
    {
        const float4* wr0 = (const float4*)(w1 + (size_t)t * 128);
        const float4* wr1 = (const float4*)(w1 + (size_t)(t + 128) * 128);
        float bb0 = b1[t], bb1 = b1[t + 128];
        u64 acc0[16], acc1[16];
        #pragma unroll
        for (int j = 0; j < 16; j++) { acc0[j] = pk2(bb0, bb0); acc1[j] = pk2(bb1, bb1); }

        #pragma unroll 2
        for (int dc = 0; dc < 32; dc++) {
            float4 wa = wr0[dc];
            float4 wb = wr1[dc];
            float was[4] = {wa.x, wa.y, wa.z, wa.w};
            float wbs[4] = {wb.x, wb.y, wb.z, wb.w};
            #pragma unroll
            for (int s4 = 0; s4 < 4; s4++) {
                int d = dc * 4 + s4;
                u64 wp0 = pk2(was[s4], was[s4]);
                u64 wp1 = pk2(wbs[s4], wbs[s4]);
                const ulonglong2* xr = (const ulonglong2*)(sm_hT + d * HT);
                #pragma unroll
                for (int i = 0; i < 8; i++) {
                    ulonglong2 xp = xr[i];           // LDS.128 broadcast: tokens 4i..4i+3
                    acc0[2*i    ] = fma2(xp.x, wp0, acc0[2*i    ]);
                    acc0[2*i + 1] = fma2(xp.y, wp0, acc0[2*i + 1]);
                    acc1[2*i    ] = fma2(xp.x, wp1, acc1[2*i    ]);
                    acc1[2*i + 1] = fma2(xp.y, wp1, acc1[2*i + 1]);
                }
            }
        }
        float* o0 = sm_x2T + t * HT;
        float* o1 = sm_x2T + (t + 128) * HT;
        #pragma unroll
        for (int j = 0; j < 16; j++) {
            float lo, hi;
            upk2(acc0[j], lo, hi);
            o0[2*j] = gelu_f(lo); o0[2*j + 1] = gelu_f(hi);
            upk2(acc1[j], lo, hi);
            o1[2*j] = gelu_f(lo); o1[2*j + 1] = gelu_f(hi);
        }
    }
    __syncthreads();

    // ---- Phase 4: h2[k][d] = gelu(x2 @ w2^T + b2); fused mean/max pool over k ----
    float msum, mmax;
    {
        const float4* wr = (const float4*)(w2 + (size_t)t * 256);
        float bb = b2[t];
        u64 acc[16];
        #pragma unroll
        for (int j = 0; j < 16; j++) acc[j] = pk2(bb, bb);

        for (int fc = 0; fc < 64; fc++) {
            float4 w = wr[fc];
            float ws[4] = {w.x, w.y, w.z, w.w};
            #pragma unroll
            for (int s4 = 0; s4 < 4; s4++) {
                int f = fc * 4 + s4;
                u64 wp = pk2(ws[s4], ws[s4]);
                const ulonglong2* xr = (const ulonglong2*)(sm_x2T + f * HT);
                #pragma unroll
                for (int i = 0; i < 8; i++) {
                    ulonglong2 xp = xr[i];
                    acc[2*i    ] = fma2(xp.x, wp, acc[2*i    ]);
                    acc[2*i + 1] = fma2(xp.y, wp, acc[2*i + 1]);
                }
            }
        }
        msum = 0.0f; mmax = -INFINITY;
        #pragma unroll
        for (int j = 0; j < 16; j++) {
            float lo, hi; upk2(acc[j], lo, hi);
            float g0 = gelu_f(lo), g1 = gelu_f(hi);
            msum += g0 + g1;
            mmax = fmaxf(mmax, fmaxf(g0, g1));
        }
    }
    __syncthreads();                 // all x2T reads done before pool overlay write
    sm_pool[t]       = msum * (1.0f / 32.0f);
    sm_pool[128 + t] = mmax;
    __syncthreads();

    // ---- Phase 5: head LayerNorm over 256 ----
    float pa = sm_pool[t], pb = sm_pool[128 + t];
    {
        float s = pa + pb, s2 = pa * pa + pb * pb;
        #pragma unroll
        for (int o = 16; o; o >>= 1) {
            s  += __shfl_xor_sync(0xffffffffu, s,  o);
            s2 += __shfl_xor_sync(0xffffffffu, s2, o);
        }
        if (lane == 0) { sm_red[wid] = s; sm_red[8 + wid] = s2; }
        __syncthreads();
        if (t == 0) {
            float S  = sm_red[0] + sm_red[1] + sm_red[2] + sm_red[3];
            float S2 = sm_red[8] + sm_red[9] + sm_red[10] + sm_red[11];
            float m  = S * (1.0f / 256.0f);
            sm_sc[12] = m;
            sm_sc[13] = rsqrtf(S2 * (1.0f / 256.0f) - m * m + 1e-5f);
        }
        __syncthreads();
        float m = sm_sc[12], inv = sm_sc[13];
        sm_pn[t]       = (pa - m) * inv * hln_g[t]       + hln_b[t];
        sm_pn[128 + t] = (pb - m) * inv * hln_g[128 + t] + hln_b[128 + t];
    }
    __syncthreads();

    // ---- Phase 6+7: head MLP GEMV (f0=t, f1=t+128) + final projection + denorm ----
    {
        const float4* wr0 = (const float4*)(hw1 + (size_t)t * 256);
        const float4* wr1 = (const float4*)(hw1 + (size_t)(t + 128) * 256);
        const ulonglong2* pn2 = (const ulonglong2*)sm_pn;
        u64 a0 = 0ull, a1 = 0ull;  // bit pattern of {0.f,0.f}
        #pragma unroll 4
        for (int c = 0; c < 64; c++) {
            float4 wa = wr0[c];
            float4 wb = wr1[c];
            ulonglong2 xp = pn2[c];   // {pn[4c],pn[4c+1]} , {pn[4c+2],pn[4c+3]}
            a0 = fma2(xp.x, pk2(wa.x, wa.y), a0);
            a0 = fma2(xp.y, pk2(wa.z, wa.w), a0);
            a1 = fma2(xp.x, pk2(wb.x, wb.y), a1);
            a1 = fma2(xp.y, pk2(wb.z, wb.w), a1);
        }
        float l0, h0, l1, h1;
        upk2(a0, l0, h0); upk2(a1, l1, h1);
        float p0 = gelu_f(l0 + h0 + hb1[t]);
        float p1 = gelu_f(l1 + h1 + hb1[128 + t]);
        float contrib = p0 * hw2[t] + p1 * hw2[128 + t];
        #pragma unroll
        for (int o = 16; o; o >>= 1)
            contrib += __shfl_xor_sync(0xffffffffu, contrib, o);
        if (lane == 0) sm_red[wid] = contrib;
        __syncthreads();
        if (t == 0) {
            float S = sm_red[0] + sm_red[1] + sm_red[2] + sm_red[3] + hb2[0];
            out[q] = S * sm_sc[1] + sm_sc[0];   // * sigma + mu
        }
    }
}

extern "C" void kernel_launch(void* const* d_in, const int* in_sizes, int n_in,
                              void* d_out, int out_size)
{
    const float* xyt_q      = (const float*)d_in[0];
    const float* obs_coords = (const float*)d_in[1];
    const float* obs_vals   = (const float*)d_in[2];
    const int*   nb_idx     = (const int*  )d_in[3];
    const float* log_gammas = (const float*)d_in[4];
    const float* w_in       = (const float*)d_in[5];
    const float* b_in       = (const float*)d_in[6];
    const float* ln1_g      = (const float*)d_in[7];
    const float* ln1_b      = (const float*)d_in[8];
    const float* w1         = (const float*)d_in[9];
    const float* b1         = (const float*)d_in[10];
    const float* w2         = (const float*)d_in[11];
    const float* b2         = (const float*)d_in[12];
    const float* hln_g      = (const float*)d_in[13];
    const float* hln_b      = (const float*)d_in[14];
    const float* hw1        = (const float*)d_in[15];
    const float* hb1        = (const float*)d_in[16];
    const float* hw2        = (const float*)d_in[17];
    const float* hb2        = (const float*)d_in[18];
    float* out = (float*)d_out;

    int Q = in_sizes[0] / 3;   // xyt_q is [Q,3]

    cudaFuncSetAttribute(ff_fused_kernel,
                         cudaFuncAttributeMaxDynamicSharedMemorySize, SMEM_BYTES);

    ff_fused_kernel<<<Q, 128, SMEM_BYTES>>>(
        xyt_q, obs_coords, obs_vals, nb_idx, log_gammas,
        w_in, b_in, ln1_g, ln1_b, w1, b1, w2, b2,
        hln_g, hln_b, hw1, hb1, hw2, hb2, out);
}

// round 7
// speedup vs baseline: 2.7731x; 2.7731x over previous
#include <cuda_runtime.h>
#include <math.h>

typedef unsigned long long u64;

__device__ __forceinline__ u64 pk2(float lo, float hi) {
    u64 r; asm("mov.b64 %0, {%1, %2};" : "=l"(r) : "f"(lo), "f"(hi)); return r;
}
__device__ __forceinline__ void upk2(u64 v, float& lo, float& hi) {
    asm("mov.b64 {%0, %1}, %2;" : "=f"(lo), "=f"(hi) : "l"(v));
}
// packed fp32x2 FMA (Blackwell): d = a*b + c on both 32-bit lanes
__device__ __forceinline__ u64 fma2(u64 a, u64 b, u64 c) {
    u64 d; asm("fma.rn.f32x2 %0, %1, %2, %3;" : "=l"(d) : "l"(a), "l"(b), "l"(c)); return d;
}
__device__ __forceinline__ float gelu_f(float x) {
    return 0.5f * x * (1.0f + erff(x * 0.70710678118654752440f));
}

// ---- Transposed weight scratch (coalesced columns for the main kernel) ----
__device__ float g_w1T[128 * 256];   // w1T[d][f]  = w1[f][d]
__device__ float g_w2T[256 * 128];   // w2T[f][d]  = w2[d][f]
__device__ float g_hw1T[256 * 256];  // hw1T[c][f] = hw1[f][c]

__global__ void __launch_bounds__(256)
transpose_weights(const float* __restrict__ w1, const float* __restrict__ w2,
                  const float* __restrict__ hw1)
{
    int i = blockIdx.x * blockDim.x + threadIdx.x;   // 0 .. 65535
    if (i < 256 * 128) {
        // w1 [256][128]
        int f = i >> 7, d = i & 127;
        g_w1T[d * 256 + f] = w1[i];
        // w2 [128][256]
        int d2 = i >> 8, f2 = i & 255;
        g_w2T[f2 * 128 + d2] = w2[i];
    }
    if (i < 256 * 256) {
        // hw1 [256][256]
        int f = i >> 8, c = i & 255;
        g_hw1T[c * 256 + f] = hw1[i];
    }
}

#define HT 36  // row stride (floats) for transposed activation tiles: 144B, 16B-aligned, conflict-padded

// Dynamic SMEM layout (floats):
//   [0      , 4608 )  hT   [128][36]  (token-MLP hidden, d-major)
//   [4608   , 13824)  x2T  [256][36]  (expanded hidden, f-major)  -- overlaid later by pool[256], pn[256]
//   [13824  , 13952)  tok  [32][4]
//   [13952  , 14080)  ln1_g
//   [14080  , 14208)  ln1_b
//   [14208  , 14224)  red
//   [14224  , 14240)  sc
#define SMEM_FLOATS 14240
#define SMEM_BYTES  (SMEM_FLOATS * 4)

__global__ void __launch_bounds__(128, 4)
ff_fused_kernel(const float* __restrict__ xyt_q, const float* __restrict__ obs_coords,
                const float* __restrict__ obs_vals, const int* __restrict__ nb_idx,
                const float* __restrict__ log_gammas,
                const float* __restrict__ w_in, const float* __restrict__ b_in,
                const float* __restrict__ ln1_g, const float* __restrict__ ln1_b,
                const float* __restrict__ b1, const float* __restrict__ b2,
                const float* __restrict__ hln_g, const float* __restrict__ hln_b,
                const float* __restrict__ hb1,
                const float* __restrict__ hw2, const float* __restrict__ hb2,
                float* __restrict__ out)
{
    extern __shared__ float sm[];
    float* sm_hT   = sm;
    float* sm_x2T  = sm + 4608;
    float* sm_pool = sm_x2T;          // reuse (after x2T consumed)
    float* sm_pn   = sm_x2T + 256;    // reuse
    float* sm_tok  = sm + 13824;
    float* sm_g    = sm + 13952;
    float* sm_b    = sm + 14080;
    float* sm_red  = sm + 14208;
    float* sm_sc   = sm + 14224;

    const int t    = threadIdx.x;
    const int q    = blockIdx.x;
    const int lane = t & 31;
    const int wid  = t >> 5;

    // ---- Phase 0a: preload LN1 params + query coords/gammas ----
    sm_g[t] = ln1_g[t];
    sm_b[t] = ln1_b[t];
    if (t < 3) {
        sm_sc[4 + t] = xyt_q[q * 3 + t];
        sm_sc[8 + t] = expf(log_gammas[t]);
    }
    __syncthreads();

    // ---- Phase 0b: gather neighbors, mu/sigma, build tokens (warp 0) ----
    if (t < 32) {
        int idx  = nb_idx[q * 32 + t];
        float cx = obs_coords[idx * 3 + 0];
        float cy = obs_coords[idx * 3 + 1];
        float cz = obs_coords[idx * 3 + 2];
        float v  = obs_vals[idx];
        float s = v, s2 = v * v;
        #pragma unroll
        for (int o = 16; o; o >>= 1) {
            s  += __shfl_xor_sync(0xffffffffu, s,  o);
            s2 += __shfl_xor_sync(0xffffffffu, s2, o);
        }
        float mu   = s * (1.0f / 32.0f);
        float varu = fmaxf((s2 - s * mu) * (1.0f / 31.0f), 0.0f);  // unbiased (ddof=1)
        float sig  = fmaxf(sqrtf(varu), 1e-3f);
        if (t == 0) { sm_sc[0] = mu; sm_sc[1] = sig; }
        float4 tk;
        tk.x = (cx - sm_sc[4]) * sm_sc[8];
        tk.y = (cy - sm_sc[5]) * sm_sc[9];
        tk.z = (cz - sm_sc[6]) * sm_sc[10];
        tk.w = (v - mu) / sig;
        ((float4*)sm_tok)[t] = tk;
    }
    __syncthreads();

    // ---- Phase 1: h[k][d] = gelu(tokens @ w_in^T + b_in); thread = channel d ----
    {
        float4 wv = ((const float4*)w_in)[t];   // w_in row d = exactly one float4 (coalesced)
        float  bw = b_in[t];
        float* hrow = sm_hT + t * HT;
        #pragma unroll
        for (int k = 0; k < 32; k++) {
            float4 tk = ((const float4*)sm_tok)[k];
            float a = fmaf(tk.w, wv.w, fmaf(tk.z, wv.z, fmaf(tk.y, wv.y, fmaf(tk.x, wv.x, bw))));
            hrow[k] = gelu_f(a);
        }
    }
    __syncthreads();

    // ---- Phase 2: LayerNorm over D per token (warp per 8 tokens), in-place ----
    {
        #pragma unroll
        for (int kk = 0; kk < 8; kk++) {
            int k = wid * 8 + kk;
            float x0 = sm_hT[(lane      ) * HT + k];
            float x1 = sm_hT[(lane + 32 ) * HT + k];
            float x2 = sm_hT[(lane + 64 ) * HT + k];
            float x3 = sm_hT[(lane + 96 ) * HT + k];
            float s  = x0 + x1 + x2 + x3;
            float s2 = x0*x0 + x1*x1 + x2*x2 + x3*x3;
            #pragma unroll
            for (int o = 16; o; o >>= 1) {
                s  += __shfl_xor_sync(0xffffffffu, s,  o);
                s2 += __shfl_xor_sync(0xffffffffu, s2, o);
            }
            float m   = s * (1.0f / 128.0f);
            float inv = rsqrtf(s2 * (1.0f / 128.0f) - m * m + 1e-5f);
            sm_hT[(lane      ) * HT + k] = (x0 - m) * inv * sm_g[lane      ] + sm_b[lane      ];
            sm_hT[(lane + 32 ) * HT + k] = (x1 - m) * inv * sm_g[lane + 32 ] + sm_b[lane + 32 ];
            sm_hT[(lane + 64 ) * HT + k] = (x2 - m) * inv * sm_g[lane + 64 ] + sm_b[lane + 64 ];
            sm_hT[(lane + 96 ) * HT + k] = (x3 - m) * inv * sm_g[lane + 96 ] + sm_b[lane + 96 ];
        }
    }
    __syncthreads();

    // ---- Phase 3: x2[k][f] = gelu(xn @ w1^T + b1); thread owns f0=t, f1=t+128 ----
    // Weights read COLUMN-WISE from w1T: warp lanes hit 32 consecutive floats
    // = one fully-consumed 128B line = 1 L1 wavefront (was 32).
    {
        const float* wc0 = g_w1T + t;          // column f0 = t (row stride 256)
        const float* wc1 = g_w1T + t + 128;    // column f1 = t+128
        float bb0 = b1[t], bb1 = b1[t + 128];
        u64 acc0[16], acc1[16];
        #pragma unroll
        for (int j = 0; j < 16; j++) { acc0[j] = pk2(bb0, bb0); acc1[j] = pk2(bb1, bb1); }

        #pragma unroll 4
        for (int d = 0; d < 128; d++) {
            float w0 = wc0[d << 8];
            float w1v = wc1[d << 8];
            u64 wp0 = pk2(w0, w0);
            u64 wp1 = pk2(w1v, w1v);
            const ulonglong2* xr = (const ulonglong2*)(sm_hT + d * HT);
            #pragma unroll
            for (int i = 0; i < 8; i++) {
                ulonglong2 xp = xr[i];           // LDS.128 broadcast: tokens 4i..4i+3
                acc0[2*i    ] = fma2(xp.x, wp0, acc0[2*i    ]);
                acc0[2*i + 1] = fma2(xp.y, wp0, acc0[2*i + 1]);
                acc1[2*i    ] = fma2(xp.x, wp1, acc1[2*i    ]);
                acc1[2*i + 1] = fma2(xp.y, wp1, acc1[2*i + 1]);
            }
        }
        float2* o0 = (float2*)(sm_x2T + t * HT);
        float2* o1 = (float2*)(sm_x2T + (t + 128) * HT);
        #pragma unroll
        for (int j = 0; j < 16; j++) {
            float lo, hi;
            upk2(acc0[j], lo, hi);
            o0[j] = make_float2(gelu_f(lo), gelu_f(hi));
            upk2(acc1[j], lo, hi);
            o1[j] = make_float2(gelu_f(lo), gelu_f(hi));
        }
    }
    __syncthreads();

    // ---- Phase 4: h2[k][d] = gelu(x2 @ w2^T + b2); fused mean/max pool over k ----
    float msum, mmax;
    {
        const float* wc = g_w2T + t;           // column d = t (row stride 128)
        float bb = b2[t];
        u64 acc[16];
        #pragma unroll
        for (int j = 0; j < 16; j++) acc[j] = pk2(bb, bb);

        #pragma unroll 4
        for (int f = 0; f < 256; f++) {
            float w = wc[f << 7];
            u64 wp = pk2(w, w);
            const ulonglong2* xr = (const ulonglong2*)(sm_x2T + f * HT);
            #pragma unroll
            for (int i = 0; i < 8; i++) {
                ulonglong2 xp = xr[i];
                acc[2*i    ] = fma2(xp.x, wp, acc[2*i    ]);
                acc[2*i + 1] = fma2(xp.y, wp, acc[2*i + 1]);
            }
        }
        msum = 0.0f; mmax = -INFINITY;
        #pragma unroll
        for (int j = 0; j < 16; j++) {
            float lo, hi; upk2(acc[j], lo, hi);
            float g0 = gelu_f(lo), g1 = gelu_f(hi);
            msum += g0 + g1;
            mmax = fmaxf(mmax, fmaxf(g0, g1));
        }
    }
    __syncthreads();                 // all x2T reads done before pool overlay write
    sm_pool[t]       = msum * (1.0f / 32.0f);
    sm_pool[128 + t] = mmax;
    __syncthreads();

    // ---- Phase 5: head LayerNorm over 256 ----
    float pa = sm_pool[t], pb = sm_pool[128 + t];
    {
        float s = pa + pb, s2 = pa * pa + pb * pb;
        #pragma unroll
        for (int o = 16; o; o >>= 1) {
            s  += __shfl_xor_sync(0xffffffffu, s,  o);
            s2 += __shfl_xor_sync(0xffffffffu, s2, o);
        }
        if (lane == 0) { sm_red[wid] = s; sm_red[8 + wid] = s2; }
        __syncthreads();
        if (t == 0) {
            float S  = sm_red[0] + sm_red[1] + sm_red[2] + sm_red[3];
            float S2 = sm_red[8] + sm_red[9] + sm_red[10] + sm_red[11];
            float m  = S * (1.0f / 256.0f);
            sm_sc[12] = m;
            sm_sc[13] = rsqrtf(S2 * (1.0f / 256.0f) - m * m + 1e-5f);
        }
        __syncthreads();
        float m = sm_sc[12], inv = sm_sc[13];
        sm_pn[t]       = (pa - m) * inv * hln_g[t]       + hln_b[t];
        sm_pn[128 + t] = (pb - m) * inv * hln_g[128 + t] + hln_b[128 + t];
    }
    __syncthreads();

    // ---- Phase 6+7: head MLP GEMV (f0=t, f1=t+128) + final projection + denorm ----
    // Coalesced columns of hw1T; c-pairs packed into fma2.
    {
        const float* hc0 = g_hw1T + t;
        const float* hc1 = g_hw1T + t + 128;
        const u64* pn2 = (const u64*)sm_pn;
        u64 a0 = 0ull, a1 = 0ull;  // bit pattern of {0.f,0.f}
        #pragma unroll 8
        for (int c2 = 0; c2 < 128; c2++) {
            int r0 = (2 * c2) << 8;
            int r1 = (2 * c2 + 1) << 8;
            float wa0 = hc0[r0], wa1 = hc0[r1];
            float wb0 = hc1[r0], wb1 = hc1[r1];
            u64 xp = pn2[c2];                   // {pn[2c2], pn[2c2+1]}
            a0 = fma2(xp, pk2(wa0, wa1), a0);
            a1 = fma2(xp, pk2(wb0, wb1), a1);
        }
        float l0, h0, l1, h1;
        upk2(a0, l0, h0); upk2(a1, l1, h1);
        float p0 = gelu_f(l0 + h0 + hb1[t]);
        float p1 = gelu_f(l1 + h1 + hb1[128 + t]);
        float contrib = p0 * hw2[t] + p1 * hw2[128 + t];
        #pragma unroll
        for (int o = 16; o; o >>= 1)
            contrib += __shfl_xor_sync(0xffffffffu, contrib, o);
        if (lane == 0) sm_red[wid] = contrib;
        __syncthreads();
        if (t == 0) {
            float S = sm_red[0] + sm_red[1] + sm_red[2] + sm_red[3] + hb2[0];
            out[q] = S * sm_sc[1] + sm_sc[0];   // * sigma + mu
        }
    }
}

extern "C" void kernel_launch(void* const* d_in, const int* in_sizes, int n_in,
                              void* d_out, int out_size)
{
    const float* xyt_q      = (const float*)d_in[0];
    const float* obs_coords = (const float*)d_in[1];
    const float* obs_vals   = (const float*)d_in[2];
    const int*   nb_idx     = (const int*  )d_in[3];
    const float* log_gammas = (const float*)d_in[4];
    const float* w_in       = (const float*)d_in[5];
    const float* b_in       = (const float*)d_in[6];
    const float* ln1_g      = (const float*)d_in[7];
    const float* ln1_b      = (const float*)d_in[8];
    const float* w1         = (const float*)d_in[9];
    const float* b1         = (const float*)d_in[10];
    const float* w2         = (const float*)d_in[11];
    const float* b2         = (const float*)d_in[12];
    const float* hln_g      = (const float*)d_in[13];
    const float* hln_b      = (const float*)d_in[14];
    const float* hw1        = (const float*)d_in[15];
    const float* hb1        = (const float*)d_in[16];
    const float* hw2        = (const float*)d_in[17];
    const float* hb2        = (const float*)d_in[18];
    float* out = (float*)d_out;

    int Q = in_sizes[0] / 3;   // xyt_q is [Q,3]

    transpose_weights<<<256, 256>>>(w1, w2, hw1);

    cudaFuncSetAttribute(ff_fused_kernel,
                         cudaFuncAttributeMaxDynamicSharedMemorySize, SMEM_BYTES);

    ff_fused_kernel<<<Q, 128, SMEM_BYTES>>>(
        xyt_q, obs_coords, obs_vals, nb_idx, log_gammas,
        w_in, b_in, ln1_g, ln1_b, b1, b2,
        hln_g, hln_b, hb1, hw2, hb2, out);
}

// round 8
// speedup vs baseline: 3.6337x; 1.3104x over previous
#include <cuda_runtime.h>
#include <math.h>

typedef unsigned long long u64;

__device__ __forceinline__ u64 pk2(float lo, float hi) {
    u64 r; asm("mov.b64 %0, {%1, %2};" : "=l"(r) : "f"(lo), "f"(hi)); return r;
}
__device__ __forceinline__ void upk2(u64 v, float& lo, float& hi) {
    asm("mov.b64 {%0, %1}, %2;" : "=f"(lo), "=f"(hi) : "l"(v));
}
// packed fp32x2 FMA (Blackwell): d = a*b + c on both 32-bit lanes
__device__ __forceinline__ u64 fma2(u64 a, u64 b, u64 c) {
    u64 d; asm("fma.rn.f32x2 %0, %1, %2, %3;" : "=l"(d) : "l"(a), "l"(b), "l"(c)); return d;
}
__device__ __forceinline__ float gelu_f(float x) {
    return 0.5f * x * (1.0f + erff(x * 0.70710678118654752440f));
}

// ---- Transposed weight scratch (coalesced columns) ----
__device__ float g_w1T[128 * 256];   // w1T[d][f]  = w1[f][d]
__device__ float g_w2T[256 * 128];   // w2T[f][d]  = w2[d][f]
__device__ float g_hw1T[256 * 256];  // hw1T[c][f] = hw1[f][c]
// ---- Inter-kernel scratch ----
#define MAXQ 32768
__device__ float g_pooled[MAXQ * 256];
__device__ float g_mu[MAXQ];
__device__ float g_sig[MAXQ];

__global__ void __launch_bounds__(256)
transpose_weights(const float* __restrict__ w1, const float* __restrict__ w2,
                  const float* __restrict__ hw1)
{
    int i = blockIdx.x * blockDim.x + threadIdx.x;   // 0 .. 65535
    if (i < 256 * 128) {
        int f = i >> 7, d = i & 127;
        g_w1T[d * 256 + f] = w1[i];      // w1 [256][128]
        int d2 = i >> 8, f2 = i & 255;
        g_w2T[f2 * 128 + d2] = w2[i];    // w2 [128][256]
    }
    if (i < 256 * 256) {
        int f = i >> 8, c = i & 255;
        g_hw1T[c * 256 + f] = hw1[i];    // hw1 [256][256]
    }
}

#define HT 36  // row stride (floats): 144B, 16B-aligned, conflict-padded

// Dynamic SMEM layout (floats):
//   [0      , 4608 )  hT   [128][36]  (token-MLP hidden, d-major; reused as pool partials)
//   [4608   , 13824)  x2T  [256][36]  (expanded hidden, f-major)
//   [13824  , 13952)  tok  [32][4]
//   [13952  , 14080)  ln1_g
//   [14080  , 14208)  ln1_b
//   [14208  , 14240)  sc
#define SMEM_FLOATS 14240
#define SMEM_BYTES  (SMEM_FLOATS * 4)

__global__ void __launch_bounds__(128, 4)
ff_body_kernel(const float* __restrict__ xyt_q, const float* __restrict__ obs_coords,
               const float* __restrict__ obs_vals, const int* __restrict__ nb_idx,
               const float* __restrict__ log_gammas,
               const float* __restrict__ w_in, const float* __restrict__ b_in,
               const float* __restrict__ ln1_g, const float* __restrict__ ln1_b,
               const float* __restrict__ b1, const float* __restrict__ b2)
{
    extern __shared__ float sm[];
    float* sm_hT   = sm;
    float* sm_x2T  = sm + 4608;
    float* sm_tok  = sm + 13824;
    float* sm_g    = sm + 13952;
    float* sm_b    = sm + 14080;
    float* sm_sc   = sm + 14208;

    const int t    = threadIdx.x;
    const int q    = blockIdx.x;
    const int lane = t & 31;
    const int wid  = t >> 5;

    // ---- Phase 0a: preload LN1 params + query coords/gammas ----
    sm_g[t] = ln1_g[t];
    sm_b[t] = ln1_b[t];
    if (t < 3) {
        sm_sc[4 + t] = xyt_q[q * 3 + t];
        sm_sc[8 + t] = expf(log_gammas[t]);
    }
    __syncthreads();

    // ---- Phase 0b: gather neighbors, mu/sigma, build tokens (warp 0) ----
    if (t < 32) {
        int idx  = nb_idx[q * 32 + t];
        float cx = obs_coords[idx * 3 + 0];
        float cy = obs_coords[idx * 3 + 1];
        float cz = obs_coords[idx * 3 + 2];
        float v  = obs_vals[idx];
        float s = v, s2 = v * v;
        #pragma unroll
        for (int o = 16; o; o >>= 1) {
            s  += __shfl_xor_sync(0xffffffffu, s,  o);
            s2 += __shfl_xor_sync(0xffffffffu, s2, o);
        }
        float mu   = s * (1.0f / 32.0f);
        float varu = fmaxf((s2 - s * mu) * (1.0f / 31.0f), 0.0f);  // unbiased (ddof=1)
        float sig  = fmaxf(sqrtf(varu), 1e-3f);
        if (t == 0) { sm_sc[0] = mu; sm_sc[1] = sig; g_mu[q] = mu; g_sig[q] = sig; }
        float4 tk;
        tk.x = (cx - sm_sc[4]) * sm_sc[8];
        tk.y = (cy - sm_sc[5]) * sm_sc[9];
        tk.z = (cz - sm_sc[6]) * sm_sc[10];
        tk.w = (v - mu) / sig;
        ((float4*)sm_tok)[t] = tk;
    }
    __syncthreads();

    // ---- Phase 1: h[k][d] = gelu(tokens @ w_in^T + b_in); thread = channel d ----
    {
        float4 wv = ((const float4*)w_in)[t];
        float  bw = b_in[t];
        float* hrow = sm_hT + t * HT;
        #pragma unroll
        for (int k = 0; k < 32; k++) {
            float4 tk = ((const float4*)sm_tok)[k];
            float a = fmaf(tk.w, wv.w, fmaf(tk.z, wv.z, fmaf(tk.y, wv.y, fmaf(tk.x, wv.x, bw))));
            hrow[k] = gelu_f(a);
        }
    }
    __syncthreads();

    // ---- Phase 2: LayerNorm over D per token (warp per 8 tokens), in-place ----
    {
        #pragma unroll
        for (int kk = 0; kk < 8; kk++) {
            int k = wid * 8 + kk;
            float x0 = sm_hT[(lane      ) * HT + k];
            float x1 = sm_hT[(lane + 32 ) * HT + k];
            float x2 = sm_hT[(lane + 64 ) * HT + k];
            float x3 = sm_hT[(lane + 96 ) * HT + k];
            float s  = x0 + x1 + x2 + x3;
            float s2 = x0*x0 + x1*x1 + x2*x2 + x3*x3;
            #pragma unroll
            for (int o = 16; o; o >>= 1) {
                s  += __shfl_xor_sync(0xffffffffu, s,  o);
                s2 += __shfl_xor_sync(0xffffffffu, s2, o);
            }
            float m   = s * (1.0f / 128.0f);
            float inv = rsqrtf(s2 * (1.0f / 128.0f) - m * m + 1e-5f);
            sm_hT[(lane      ) * HT + k] = (x0 - m) * inv * sm_g[lane      ] + sm_b[lane      ];
            sm_hT[(lane + 32 ) * HT + k] = (x1 - m) * inv * sm_g[lane + 32 ] + sm_b[lane + 32 ];
            sm_hT[(lane + 64 ) * HT + k] = (x2 - m) * inv * sm_g[lane + 64 ] + sm_b[lane + 64 ];
            sm_hT[(lane + 96 ) * HT + k] = (x3 - m) * inv * sm_g[lane + 96 ] + sm_b[lane + 96 ];
        }
    }
    __syncthreads();

    // ---- Phase 3: x2[k][f] = gelu(xn @ w1^T + b1) ----
    // Thread: features {2a, 2a+1, 128+2a, 129+2a} (a = t&63), token half h = t>>6.
    // LDS:FMA ratio 1:8 (was 1:4); weights as coalesced float2 pairs.
    {
        const int a = t & 63;
        const int h = t >> 6;
        float2 bb0 = ((const float2*)b1)[a];
        float2 bb1 = ((const float2*)b1)[a + 64];
        u64 acc[4][8];
        #pragma unroll
        for (int j = 0; j < 8; j++) {
            acc[0][j] = pk2(bb0.x, bb0.x);
            acc[1][j] = pk2(bb0.y, bb0.y);
            acc[2][j] = pk2(bb1.x, bb1.x);
            acc[3][j] = pk2(bb1.y, bb1.y);
        }
        #pragma unroll 4
        for (int d = 0; d < 128; d++) {
            float2 w0 = ((const float2*)(g_w1T + (d << 8)      ))[a];
            float2 w1v= ((const float2*)(g_w1T + (d << 8) + 128))[a];
            u64 wp0 = pk2(w0.x, w0.x);
            u64 wp1 = pk2(w0.y, w0.y);
            u64 wp2 = pk2(w1v.x, w1v.x);
            u64 wp3 = pk2(w1v.y, w1v.y);
            const ulonglong2* xr = (const ulonglong2*)(sm_hT + d * HT + 16 * h);
            #pragma unroll
            for (int i = 0; i < 4; i++) {
                ulonglong2 xp = xr[i];   // tokens 16h+4i .. 16h+4i+3
                acc[0][2*i  ] = fma2(xp.x, wp0, acc[0][2*i  ]);
                acc[0][2*i+1] = fma2(xp.y, wp0, acc[0][2*i+1]);
                acc[1][2*i  ] = fma2(xp.x, wp1, acc[1][2*i  ]);
                acc[1][2*i+1] = fma2(xp.y, wp1, acc[1][2*i+1]);
                acc[2][2*i  ] = fma2(xp.x, wp2, acc[2][2*i  ]);
                acc[2][2*i+1] = fma2(xp.y, wp2, acc[2][2*i+1]);
                acc[3][2*i  ] = fma2(xp.x, wp3, acc[3][2*i  ]);
                acc[3][2*i+1] = fma2(xp.y, wp3, acc[3][2*i+1]);
            }
        }
        int feat[4] = {2*a, 2*a + 1, 128 + 2*a, 129 + 2*a};
        #pragma unroll
        for (int ftr = 0; ftr < 4; ftr++) {
            float2* orow = (float2*)(sm_x2T + feat[ftr] * HT + 16 * h);
            #pragma unroll
            for (int j = 0; j < 8; j++) {
                float lo, hi; upk2(acc[ftr][j], lo, hi);
                orow[j] = make_float2(gelu_f(lo), gelu_f(hi));
            }
        }
    }
    __syncthreads();

    // ---- Phase 4: h2[k][d] = gelu(x2 @ w2^T + b2) + partial pools ----
    // Thread: features {2l, 2l+1, 64+2l, 65+2l} (l = lane), token quarter = wid.
    {
        const int l = lane;
        float2 bb0 = ((const float2*)b2)[l];
        float2 bb1 = ((const float2*)b2)[l + 32];
        u64 acc[4][4];
        #pragma unroll
        for (int j = 0; j < 4; j++) {
            acc[0][j] = pk2(bb0.x, bb0.x);
            acc[1][j] = pk2(bb0.y, bb0.y);
            acc[2][j] = pk2(bb1.x, bb1.x);
            acc[3][j] = pk2(bb1.y, bb1.y);
        }
        #pragma unroll 4
        for (int f = 0; f < 256; f++) {
            float2 w0 = ((const float2*)(g_w2T + (f << 7)     ))[l];
            float2 w1v= ((const float2*)(g_w2T + (f << 7) + 64))[l];
            u64 wp0 = pk2(w0.x, w0.x);
            u64 wp1 = pk2(w0.y, w0.y);
            u64 wp2 = pk2(w1v.x, w1v.x);
            u64 wp3 = pk2(w1v.y, w1v.y);
            const ulonglong2* xr = (const ulonglong2*)(sm_x2T + f * HT + 8 * wid);
            #pragma unroll
            for (int i = 0; i < 2; i++) {
                ulonglong2 xp = xr[i];   // tokens 8wid+4i .. +3
                acc[0][2*i  ] = fma2(xp.x, wp0, acc[0][2*i  ]);
                acc[0][2*i+1] = fma2(xp.y, wp0, acc[0][2*i+1]);
                acc[1][2*i  ] = fma2(xp.x, wp1, acc[1][2*i  ]);
                acc[1][2*i+1] = fma2(xp.y, wp1, acc[1][2*i+1]);
                acc[2][2*i  ] = fma2(xp.x, wp2, acc[2][2*i  ]);
                acc[2][2*i+1] = fma2(xp.y, wp2, acc[2][2*i+1]);
                acc[3][2*i  ] = fma2(xp.x, wp3, acc[3][2*i  ]);
                acc[3][2*i+1] = fma2(xp.y, wp3, acc[3][2*i+1]);
            }
        }
        // gelu + partial pools over this thread's 8 tokens, per feature
        int dfeat[4] = {2*l, 2*l + 1, 64 + 2*l, 65 + 2*l};
        float* sm_ps = sm_hT;          // [4][128] partial sums
        float* sm_pm = sm_hT + 512;    // [4][128] partial maxes
        #pragma unroll
        for (int ftr = 0; ftr < 4; ftr++) {
            float ps = 0.0f, pm = -INFINITY;
            #pragma unroll
            for (int j = 0; j < 4; j++) {
                float lo, hi; upk2(acc[ftr][j], lo, hi);
                float g0 = gelu_f(lo), g1 = gelu_f(hi);
                ps += g0 + g1;
                pm = fmaxf(pm, fmaxf(g0, g1));
            }
            sm_ps[wid * 128 + dfeat[ftr]] = ps;
            sm_pm[wid * 128 + dfeat[ftr]] = pm;
        }
    }
    __syncthreads();

    // ---- Phase 4b: reduce partials, write pooled to global ----
    {
        float* sm_ps = sm_hT;
        float* sm_pm = sm_hT + 512;
        float s  = sm_ps[t] + sm_ps[128 + t] + sm_ps[256 + t] + sm_ps[384 + t];
        float mx = fmaxf(fmaxf(sm_pm[t], sm_pm[128 + t]), fmaxf(sm_pm[256 + t], sm_pm[384 + t]));
        g_pooled[(size_t)q * 256 + t]       = s * (1.0f / 32.0f);
        g_pooled[(size_t)q * 256 + 128 + t] = mx;
    }
}

// ================= Head kernel: LN(256) + Lin(256,256)+gelu + Lin(256,1) ==========
// One CTA = 32 queries, 256 threads (thread = output feature for the GEMM).
#define K2P 36
__global__ void __launch_bounds__(256)
ff_head_kernel(const float* __restrict__ hln_g, const float* __restrict__ hln_b,
               const float* __restrict__ hb1, const float* __restrict__ hw2,
               const float* __restrict__ hb2, int Q, float* __restrict__ out)
{
    __shared__ float s_pnT[256 * K2P];   // [k][q'] normalized pooled, transposed
    __shared__ float s_hg[256];
    __shared__ float s_hb[256];

    const int t    = threadIdx.x;
    const int lane = t & 31;
    const int w8   = t >> 5;          // warp 0..7
    const int qb   = blockIdx.x * 32;

    s_hg[t] = hln_g[t];
    s_hb[t] = hln_b[t];
    __syncthreads();

    // ---- LN per query (warp per query, 4 queries per warp) ----
    #pragma unroll
    for (int it = 0; it < 4; it++) {
        int qq = w8 * 4 + it;         // 0..31
        int q  = qb + qq;
        if (q < Q) {
            const float* row = g_pooled + (size_t)q * 256;
            float x[8];
            float s = 0.0f, s2 = 0.0f;
            #pragma unroll
            for (int j = 0; j < 8; j++) {
                x[j] = row[lane + 32 * j];
                s += x[j]; s2 += x[j] * x[j];
            }
            #pragma unroll
            for (int o = 16; o; o >>= 1) {
                s  += __shfl_xor_sync(0xffffffffu, s,  o);
                s2 += __shfl_xor_sync(0xffffffffu, s2, o);
            }
            float m   = s * (1.0f / 256.0f);
            float inv = rsqrtf(s2 * (1.0f / 256.0f) - m * m + 1e-5f);
            #pragma unroll
            for (int j = 0; j < 8; j++) {
                int k = lane + 32 * j;
                s_pnT[k * K2P + qq] = (x[j] - m) * inv * s_hg[k] + s_hb[k];
            }
        }
    }
    __syncthreads();

    // ---- GEMM: p[qq][f=t] = gelu( sum_k pn[qq][k] * hw1T[k][t] + hb1[t] ) ----
    u64 acc[16];
    #pragma unroll
    for (int j = 0; j < 16; j++) acc[j] = 0ull;
    #pragma unroll 2
    for (int k = 0; k < 256; k++) {
        float w = g_hw1T[(k << 8) + t];      // coalesced
        u64 wp = pk2(w, w);
        const ulonglong2* xr = (const ulonglong2*)(s_pnT + k * K2P);
        #pragma unroll
        for (int i = 0; i < 8; i++) {
            ulonglong2 xp = xr[i];           // queries 4i..4i+3 (broadcast)
            acc[2*i  ] = fma2(xp.x, wp, acc[2*i  ]);
            acc[2*i+1] = fma2(xp.y, wp, acc[2*i+1]);
        }
    }
    float hb = hb1[t];
    float ws = hw2[t];
    float v[32];
    #pragma unroll
    for (int j = 0; j < 16; j++) {
        float lo, hi; upk2(acc[j], lo, hi);
        v[2*j]   = gelu_f(lo + hb) * ws;
        v[2*j+1] = gelu_f(hi + hb) * ws;
    }
    __syncthreads();                          // all s_pnT reads done
    // scatter contributions: row f = t, col q'
    #pragma unroll
    for (int j = 0; j < 32; j++) s_pnT[t * K2P + j] = v[j];
    __syncthreads();

    // ---- final reduction over 256 features per query ----
    {
        int qq = t >> 3;          // query 0..31
        int c8 = t & 7;           // chunk 0..7 (32 features each)
        float ps = 0.0f;
        #pragma unroll 8
        for (int j = 0; j < 32; j++)
            ps += s_pnT[(c8 * 32 + j) * K2P + qq];
        ps += __shfl_xor_sync(0xffffffffu, ps, 1);
        ps += __shfl_xor_sync(0xffffffffu, ps, 2);
        ps += __shfl_xor_sync(0xffffffffu, ps, 4);
        if (c8 == 0) {
            int q = qb + qq;
            if (q < Q)
                out[q] = (ps + hb2[0]) * g_sig[q] + g_mu[q];
        }
    }
}

extern "C" void kernel_launch(void* const* d_in, const int* in_sizes, int n_in,
                              void* d_out, int out_size)
{
    const float* xyt_q      = (const float*)d_in[0];
    const float* obs_coords = (const float*)d_in[1];
    const float* obs_vals   = (const float*)d_in[2];
    const int*   nb_idx     = (const int*  )d_in[3];
    const float* log_gammas = (const float*)d_in[4];
    const float* w_in       = (const float*)d_in[5];
    const float* b_in       = (const float*)d_in[6];
    const float* ln1_g      = (const float*)d_in[7];
    const float* ln1_b      = (const float*)d_in[8];
    const float* w1         = (const float*)d_in[9];
    const float* b1         = (const float*)d_in[10];
    const float* w2         = (const float*)d_in[11];
    const float* b2         = (const float*)d_in[12];
    const float* hln_g      = (const float*)d_in[13];
    const float* hln_b      = (const float*)d_in[14];
    const float* hw1        = (const float*)d_in[15];
    const float* hb1        = (const float*)d_in[16];
    const float* hw2        = (const float*)d_in[17];
    const float* hb2        = (const float*)d_in[18];
    float* out = (float*)d_out;

    int Q = in_sizes[0] / 3;   // xyt_q is [Q,3]

    transpose_weights<<<256, 256>>>(w1, w2, hw1);

    cudaFuncSetAttribute(ff_body_kernel,
                         cudaFuncAttributeMaxDynamicSharedMemorySize, SMEM_BYTES);

    ff_body_kernel<<<Q, 128, SMEM_BYTES>>>(
        xyt_q, obs_coords, obs_vals, nb_idx, log_gammas,
        w_in, b_in, ln1_g, ln1_b, b1, b2);

    ff_head_kernel<<<(Q + 31) / 32, 256>>>(hln_g, hln_b, hb1, hw2, hb2, Q, out);
}